// round 4
// baseline (speedup 1.0000x reference)
#include <cuda_runtime.h>

// InverseHaar: input (B=16, C=256, H=128, W=128) fp32, C = 4 bands x G=64 groups.
// Output (B=16, G=64, 2H=256, 2W=256) fp32.
//
// Big-burst variant: each thread processes TWO full input rows (h0=2hh, h1=2hh+1):
//   16 front-batched float2 loads (4 bands x 2 rows x 2 half-rows),
//   8 float4 stores, each warp-contiguous 512B (4 output rows x 2 stores).

#define B_  16
#define G_  64
#define H_  128
#define W_  128
#define HW_ (H_ * W_)              // 16384
#define BAND_STRIDE_ (G_ * HW_)    // 1048576 floats between bands (same b)
#define OW_ (2 * W_)               // 256 output width
#define OH_ (2 * H_)               // 256 output height

__device__ __forceinline__ void haar4(float2 a, float2 h, float2 v, float2 d,
                                      float4& top, float4& bot)
{
    const float Q = 0.25f;
    float tlx = (a.x + h.x + v.x + d.x) * Q;
    float trx = (a.x - h.x + v.x - d.x) * Q;
    float blx = (a.x + h.x - v.x - d.x) * Q;
    float brx = (a.x - h.x - v.x + d.x) * Q;
    float tly = (a.y + h.y + v.y + d.y) * Q;
    float try_ = (a.y - h.y + v.y - d.y) * Q;
    float bly = (a.y + h.y - v.y - d.y) * Q;
    float bry = (a.y - h.y - v.y + d.y) * Q;
    top = make_float4(tlx, trx, tly, try_);
    bot = make_float4(blx, brx, bly, bry);
}

__global__ void __launch_bounds__(256) inverse_haar_kernel(
    const float2* __restrict__ in,   // viewed as float2
    float4* __restrict__ out)        // viewed as float4
{
    int idx = blockIdx.x * blockDim.x + threadIdx.x;
    // total threads = B*G*(H/2)*32 = 2,097,152

    int l  = idx & 31;            // pair index within half-row
    int t  = idx >> 5;
    int hh = t & 63;              // h-pair index (H/2 = 64)
    t >>= 6;
    int g  = t & (G_ - 1);
    int b  = t >> 6;

    int h0 = 2 * hh;              // two consecutive input rows

    // Input bases in float2 units (band a); bands at +S, +2S, +3S.
    long base0 = ((long)(b * 4) * G_ + g) * (HW_ / 2) + (long)h0 * (W_ / 2) + l;
    long base1 = base0 + (W_ / 2);       // row h0+1
    const long S = BAND_STRIDE_ / 2;     // band stride in float2 units
    const int  HF = 32;                  // second half-row offset (w=64)

    // 16 front-batched streaming loads
    float2 a00 = __ldcs(&in[base0]);
    float2 a01 = __ldcs(&in[base0 + HF]);
    float2 a10 = __ldcs(&in[base1]);
    float2 a11 = __ldcs(&in[base1 + HF]);
    float2 h00 = __ldcs(&in[base0 + S]);
    float2 h01 = __ldcs(&in[base0 + S + HF]);
    float2 h10 = __ldcs(&in[base1 + S]);
    float2 h11 = __ldcs(&in[base1 + S + HF]);
    float2 v00 = __ldcs(&in[base0 + 2 * S]);
    float2 v01 = __ldcs(&in[base0 + 2 * S + HF]);
    float2 v10 = __ldcs(&in[base1 + 2 * S]);
    float2 v11 = __ldcs(&in[base1 + 2 * S + HF]);
    float2 d00 = __ldcs(&in[base0 + 3 * S]);
    float2 d01 = __ldcs(&in[base0 + 3 * S + HF]);
    float2 d10 = __ldcs(&in[base1 + 3 * S]);
    float2 d11 = __ldcs(&in[base1 + 3 * S + HF]);

    float4 t00, b00, t01, b01, t10, b10, t11, b11;
    haar4(a00, h00, v00, d00, t00, b00);   // row h0, half 0
    haar4(a01, h01, v01, d01, t01, b01);   // row h0, half 1
    haar4(a10, h10, v10, d10, t10, b10);   // row h1, half 0
    haar4(a11, h11, v11, d11, t11, b11);   // row h1, half 1

    // Output rows 2h0, 2h0+1, 2h0+2, 2h0+3; row = OW_/4 = 64 float4.
    long orow = (((long)(b * G_ + g) * OH_) + 2 * h0) * (OW_ / 4);

    // Warp-contiguous 512B stores: slots l (half0) and l+32 (half1) per row.
    __stcs(&out[orow + l],            t00);
    __stcs(&out[orow + 32 + l],       t01);
    __stcs(&out[orow + 64 + l],       b00);
    __stcs(&out[orow + 96 + l],       b01);
    __stcs(&out[orow + 128 + l],      t10);
    __stcs(&out[orow + 160 + l],      t11);
    __stcs(&out[orow + 192 + l],      b10);
    __stcs(&out[orow + 224 + l],      b11);
}

extern "C" void kernel_launch(void* const* d_in, const int* in_sizes, int n_in,
                              void* d_out, int out_size)
{
    const float2* in = (const float2*)d_in[0];
    float4* out = (float4*)d_out;

    int total_threads = B_ * G_ * (H_ / 2) * 32;   // 2,097,152
    int block = 256;
    int grid = total_threads / block;              // 8192
    inverse_haar_kernel<<<grid, block>>>(in, out);
}